// round 15
// baseline (speedup 1.0000x reference)
#include <cuda_runtime.h>
#include <cuda_fp16.h>
#include <cstdint>
#include <cstddef>

// ---------------------------------------------------------------------------
// MeshGNN: N=50000, E=600000, IN=16, ED=4, H=128, L=4, OUT=3
// Round 13: atomic-free aggregation. Per call: counting-sort edges by dst
// (CSR). Edge kernel writes fp16 messages contiguously in sorted order;
// agg_kernel does warp-per-node segmented sums (no atomics, no agg zeroing).
// Node kernel = R12 overlap version minus zero-writeback.
// ---------------------------------------------------------------------------

#define N_NODES 50000
#define N_EDGES 600000
#define H 128
#define IN_F 16
#define ED 4
#define N_LAYERS 4
#define N_OUT 3
#define TN 32

#define PAD  136   // node A / W2 k stride (elements)
#define PADW 264   // node W1 (K=256) stride
#define EPAD 152   // edge kernel stride: 128 ch + 16 ea block + 8 slack

#define A_BUF  19456   // 64 * EPAD * 2

// ---- edge kernel smem map (bytes)
#define SM_B1   0
#define SM_B2   512
#define SM_W1   1024     // 38912 (incl. ea rows at k=128..143)
#define SM_W2   39936    // 38912
#define SM_A    78848    // + (g*2+b)*19456
#define SM_EDGE_TOTAL 156672

// ---- fused node smem map
#define NB_B    0        // b1[128] b2[128] = 1024
#define NB_W1   1024     // 128*PADW*2 = 67584
#define NB_W2   68608    // 128*PAD*2  = 34816
#define NB_A    103424   // 128*PAD*2  = 34816
#define NB_RAW  138240   // 128*128*4  = 65536 (raw fp32 agg tile)
#define NB_TOTAL 203776

__device__ float g_h[(size_t)N_NODES * H];
__device__ float g_agg[(size_t)N_NODES * H];
__device__ float g_inv[N_NODES];
__device__ uint32_t g_hp[(size_t)N_NODES * 64];    // packed fp16 h (hi plane only)
__device__ uint32_t g_eap[(size_t)N_EDGES * 8];    // fp16 ea block (4 real + 12 zero)
__device__ int g_off[N_NODES + 1];                 // CSR offsets
__device__ int g_cnt[N_NODES];                     // scatter counters
__device__ int g_ssrc[N_EDGES];                    // sorted src
__device__ int g_sperm[N_EDGES];                   // sorted -> original edge id
__device__ uint32_t g_msg[(size_t)N_EDGES * 64];   // fp16 messages (sorted order)

// ======================= helpers ==========================================

__device__ __forceinline__ uint32_t smem_u32(const void* p) {
    uint32_t a;
    asm("{ .reg .u64 t; cvta.to.shared.u64 t, %1; cvt.u32.u64 %0, t; }"
        : "=r"(a) : "l"(p));
    return a;
}

__device__ __forceinline__ void ldsm_x4(uint32_t* r, uint32_t addr) {
    asm volatile("ldmatrix.sync.aligned.m8n8.x4.shared.b16 {%0,%1,%2,%3}, [%4];"
                 : "=r"(r[0]), "=r"(r[1]), "=r"(r[2]), "=r"(r[3]) : "r"(addr));
}

__device__ __forceinline__ void mma16816(float* c, const uint32_t* a,
                                         uint32_t b0, uint32_t b1) {
    asm volatile(
        "mma.sync.aligned.m16n8k16.row.col.f32.f16.f16.f32 "
        "{%0,%1,%2,%3}, {%4,%5,%6,%7}, {%8,%9}, {%0,%1,%2,%3};"
        : "+f"(c[0]), "+f"(c[1]), "+f"(c[2]), "+f"(c[3])
        : "r"(a[0]), "r"(a[1]), "r"(a[2]), "r"(a[3]), "r"(b0), "r"(b1));
}

__device__ __forceinline__ uint32_t packh2(float x, float y) {
    __half2 h = __floats2half2_rn(x, y);
    return *reinterpret_cast<uint32_t*>(&h);
}

#define GROUP_BAR(gid) \
    asm volatile("bar.sync %0, %1;" :: "r"(1 + (gid)), "r"(128) : "memory")

#define CP_ASYNC16(dst, src) \
    asm volatile("cp.async.ca.shared.global [%0], [%1], 16;" :: "r"(dst), "l"(src) : "memory")
#define CP_COMMIT() asm volatile("cp.async.commit_group;" ::: "memory")
#define CP_WAIT0()  asm volatile("cp.async.wait_group 0;" ::: "memory")
#define CP_WAIT1()  asm volatile("cp.async.wait_group 1;" ::: "memory")

// ======================= prologue kernels ==================================

__global__ void zero_cnt_kernel() {
    int i = blockIdx.x * blockDim.x + threadIdx.x;
    if (i < N_NODES) g_inv[i] = 0.f;
}

__global__ void deg_kernel(const int* __restrict__ dst) {
    int e = blockIdx.x * blockDim.x + threadIdx.x;
    if (e < N_EDGES) atomicAdd(&g_inv[dst[e]], 1.0f);
}

// single-block exclusive prefix scan of degrees -> g_off, g_cnt
__global__ void __launch_bounds__(1024, 1) scan_kernel() {
    __shared__ int s[1024];
    const int C = (N_NODES + 1023) / 1024;  // 49
    const int t = threadIdx.x;
    const int base = t * C;
    int sum = 0;
    for (int i = 0; i < C; i++) {
        int n = base + i;
        if (n < N_NODES) sum += (int)g_inv[n];
    }
    s[t] = sum;
    __syncthreads();
    for (int off = 1; off < 1024; off <<= 1) {
        int v = (t >= off) ? s[t - off] : 0;
        __syncthreads();
        s[t] += v;
        __syncthreads();
    }
    int run = (t == 0) ? 0 : s[t - 1];
    for (int i = 0; i < C; i++) {
        int n = base + i;
        if (n < N_NODES) {
            int d = (int)g_inv[n];
            g_off[n] = run;
            g_cnt[n] = run;
            run += d;
        }
    }
    if (t == 1023) g_off[N_NODES] = run;
}

// counting-sort scatter: sorted position p for each edge
__global__ void scatter_kernel(const int* __restrict__ src,
                               const int* __restrict__ dst) {
    int e = blockIdx.x * blockDim.x + threadIdx.x;
    if (e < N_EDGES) {
        int d = dst[e];
        int p = atomicAdd(&g_cnt[d], 1);
        g_ssrc[p] = src[e];
        g_sperm[p] = e;
    }
}

// fused: inv (after scan consumed raw degrees), pack ea
__global__ void prep_kernel(const float* __restrict__ ea) {
    const size_t gtid = (size_t)blockIdx.x * blockDim.x + threadIdx.x;
    const size_t gsz  = (size_t)gridDim.x * blockDim.x;
    for (size_t i = gtid; i < N_NODES; i += gsz)
        g_inv[i] = 1.0f / fmaxf(g_inv[i], 1.0f);
    for (size_t e = gtid; e < N_EDGES; e += gsz) {
        float4 a = *reinterpret_cast<const float4*>(ea + e * 4);
        uint4* p = reinterpret_cast<uint4*>(g_eap + e * 8);
        p[0] = make_uint4(packh2(a.x, a.y), packh2(a.z, a.w), 0u, 0u);
        p[1] = make_uint4(0u, 0u, 0u, 0u);
    }
}

// h = relu(x @ W + b); writes fp32 g_h + packed fp16 hi plane g_hp
__global__ void lin_in_kernel(const float* __restrict__ x,
                              const float* __restrict__ W,
                              const float* __restrict__ b) {
    __shared__ float sx[IN_F];
    __shared__ float sh[H];
    int n = blockIdx.x;
    if (threadIdx.x < IN_F) sx[threadIdx.x] = x[(size_t)n * IN_F + threadIdx.x];
    __syncthreads();
    int c = threadIdx.x;
    float acc = __ldg(&b[c]);
#pragma unroll
    for (int k = 0; k < IN_F; k++)
        acc = fmaf(sx[k], __ldg(&W[k * H + c]), acc);
    float v = fmaxf(acc, 0.f);
    g_h[(size_t)n * H + c] = v;
    sh[c] = v;
    __syncthreads();
    if (threadIdx.x < 64) {
        int w = threadIdx.x;
        g_hp[(size_t)n * 64 + w] = packh2(sh[2 * w], sh[2 * w + 1]);
    }
}

// stage W[k][n] fp32 transposed into WT[n][k] fp16, stride pad
__device__ __forceinline__ void stage_w_f16(char* smem, const float* __restrict__ W,
                                            int off, int kdim, int pad) {
    for (int idx = threadIdx.x; idx < kdim * H; idx += blockDim.x) {
        int k = idx >> 7, n = idx & 127;
        *reinterpret_cast<__half*>(smem + off + (n * pad + k) * 2) = __float2half(W[idx]);
    }
}

// ======================= edge kernel =======================================
// Sorted-edge tiles of 64; single-pass fp16 HMMA; contiguous fp16 message
// store (no atomics). 2 groups x 4 warps, double-buffered cp.async.

__device__ __forceinline__ void edge_prefetch(
    uint32_t sb, int gb, int srcval, int permval, int ltid) {
    const int r  = ltid >> 1;
    const int hc = (ltid & 1) * 64;
    const uint32_t* sp = g_hp + (size_t)srcval * 64 + (ltid & 1) * 32;
    uint32_t dh = sb + SM_A + (uint32_t)gb * (uint32_t)A_BUF +
                  (uint32_t)(r * EPAD + hc) * 2u;
#pragma unroll
    for (int p = 0; p < 8; p++) CP_ASYNC16(dh + 16u * p, sp + 4 * p);
    if (ltid < 64) {
        uint32_t de = sb + SM_A + (uint32_t)gb * (uint32_t)A_BUF +
                      (uint32_t)(ltid * EPAD + 128) * 2u;
        const uint32_t* ep = g_eap + (size_t)permval * 8;
        CP_ASYNC16(de, ep);
        CP_ASYNC16(de + 16u, ep + 4);
    }
}

__global__ void __launch_bounds__(256, 1)
edge_kernel(const float* __restrict__ W1, const float* __restrict__ b1,
            const float* __restrict__ W2, const float* __restrict__ b2) {
    extern __shared__ char smem[];
    const uint32_t sb = smem_u32(smem);
    float* s_b1 = reinterpret_cast<float*>(smem + SM_B1);
    float* s_b2 = reinterpret_cast<float*>(smem + SM_B2);

    const int tid  = threadIdx.x;
    const int wid  = tid >> 5;
    const int lane = tid & 31;
    const int g    = wid >> 2;
    const int lw   = wid & 3;
    const int ltid = tid & 127;

    for (int idx = tid; idx < 144 * 128; idx += 256) {
        int k = idx >> 7, n = idx & 127;
        float v = (k < 128) ? W1[k * H + n]
                : (k < 132) ? W1[(H + k - 128) * H + n] : 0.f;
        *reinterpret_cast<__half*>(smem + SM_W1 + (n * EPAD + k) * 2) = __float2half(v);
    }
    for (int idx = tid; idx < 128 * 128; idx += 256) {
        int k = idx >> 7, n = idx & 127;
        *reinterpret_cast<__half*>(smem + SM_W2 + (n * EPAD + k) * 2) =
            __float2half(W2[idx]);
    }
    if (tid < 128) {
        s_b1[tid] = b1[tid];
        s_b2[tid] = b2[tid];
    }
    __syncthreads();

    const int m0 = lw * 16;
    const int rq = lane >> 2;
    const int cp = (lane & 3) * 2;
    const uint32_t aOffLane = ((uint32_t)(m0 + (lane & 15)) * EPAD + 8u * (lane >> 4)) * 2u;
    const uint32_t bOffLane = ((uint32_t)((lane & 7) + 8 * ((lane >> 3) & 1)) * EPAD +
                               8u * (lane >> 4)) * 2u;

    const int NT = N_EDGES / 64;  // 9375
    const int stride = gridDim.x * 2;
    int t = blockIdx.x * 2 + g;
    int buf = 0;
    int nsrc = 0, nperm = 0;

    if (t < NT) {
        nsrc  = __ldg(&g_ssrc[t * 64 + (ltid >> 1)]);
        nperm = (ltid < 64) ? __ldg(&g_sperm[t * 64 + ltid]) : 0;
        edge_prefetch(sb, g * 2, nsrc, nperm, ltid);
        CP_COMMIT();
        int t2 = t + stride;
        if (t2 < NT) {
            nsrc  = __ldg(&g_ssrc[t2 * 64 + (ltid >> 1)]);
            nperm = (ltid < 64) ? __ldg(&g_sperm[t2 * 64 + ltid]) : 0;
        }
    }

    for (; t < NT; t += stride) {
        CP_WAIT0();
        GROUP_BAR(g);

        const int tn = t + stride;
        if (tn < NT) {
            edge_prefetch(sb, g * 2 + (buf ^ 1), nsrc, nperm, ltid);
            CP_COMMIT();
            const int tnn = tn + stride;
            if (tnn < NT) {
                nsrc  = __ldg(&g_ssrc[tnn * 64 + (ltid >> 1)]);
                nperm = (ltid < 64) ? __ldg(&g_sperm[tnn * 64 + ltid]) : 0;
            }
        }

        const uint32_t bA = sb + SM_A + (uint32_t)(g * 2 + buf) * (uint32_t)A_BUF;

        float acc[16][4];
#pragma unroll
        for (int j = 0; j < 16; j++) {
            const int n = j * 8 + cp;
            acc[j][0] = s_b1[n]; acc[j][1] = s_b1[n + 1];
            acc[j][2] = s_b1[n]; acc[j][3] = s_b1[n + 1];
        }

        // GEMM1: 9 uniform k-steps (k-step 8 = ea @ W1b)
#pragma unroll
        for (int ks = 0; ks < 9; ks++) {
            const uint32_t k0b = (uint32_t)ks * 32u;
            uint32_t ah[4];
            ldsm_x4(ah, bA + aOffLane + k0b);
#pragma unroll
            for (int jj = 0; jj < 8; jj++) {
                const uint32_t bo = bOffLane + k0b + (uint32_t)jj * (16 * EPAD * 2);
                uint32_t bh[4];
                ldsm_x4(bh, sb + SM_W1 + bo);
                mma16816(acc[2 * jj],     ah, bh[0], bh[2]);
                mma16816(acc[2 * jj + 1], ah, bh[1], bh[3]);
            }
        }

        // relu + fp16 re-pack (C frags -> A frags)
        uint32_t a2[8][4];
#pragma unroll
        for (int gg = 0; gg < 8; gg++) {
            a2[gg][0] = packh2(fmaxf(acc[2 * gg][0], 0.f),     fmaxf(acc[2 * gg][1], 0.f));
            a2[gg][1] = packh2(fmaxf(acc[2 * gg][2], 0.f),     fmaxf(acc[2 * gg][3], 0.f));
            a2[gg][2] = packh2(fmaxf(acc[2 * gg + 1][0], 0.f), fmaxf(acc[2 * gg + 1][1], 0.f));
            a2[gg][3] = packh2(fmaxf(acc[2 * gg + 1][2], 0.f), fmaxf(acc[2 * gg + 1][3], 0.f));
        }

#pragma unroll
        for (int j = 0; j < 16; j++) {
            const int n = j * 8 + cp;
            acc[j][0] = s_b2[n]; acc[j][1] = s_b2[n + 1];
            acc[j][2] = s_b2[n]; acc[j][3] = s_b2[n + 1];
        }

        // GEMM2
#pragma unroll
        for (int ks = 0; ks < 8; ks++) {
            const uint32_t k0b = (uint32_t)ks * 32u;
#pragma unroll
            for (int jj = 0; jj < 8; jj++) {
                const uint32_t bo = bOffLane + k0b + (uint32_t)jj * (16 * EPAD * 2);
                uint32_t bh[4];
                ldsm_x4(bh, sb + SM_W2 + bo);
                mma16816(acc[2 * jj],     a2[ks], bh[0], bh[2]);
                mma16816(acc[2 * jj + 1], a2[ks], bh[1], bh[3]);
            }
        }

        // relu + contiguous fp16 message store (no atomics)
        {
            const int r0 = m0 + rq, r1 = r0 + 8;
            uint32_t* mp0 = g_msg + (size_t)(t * 64 + r0) * 64;
            uint32_t* mp1 = g_msg + (size_t)(t * 64 + r1) * 64;
            const int wq = lane & 3;
#pragma unroll
            for (int j = 0; j < 16; j++) {
                const int w = j * 4 + wq;
                mp0[w] = packh2(fmaxf(acc[j][0], 0.f), fmaxf(acc[j][1], 0.f));
                mp1[w] = packh2(fmaxf(acc[j][2], 0.f), fmaxf(acc[j][3], 0.f));
            }
        }
        buf ^= 1;
    }
}

// ======================= agg kernel ========================================
// Warp-per-node segmented sum over contiguous message runs -> g_agg (fp32).
// Writes every row fully (no zeroing needed anywhere).

__global__ void __launch_bounds__(256, 4)
agg_kernel() {
    const int lane = threadIdx.x & 31;
    const int warp = (blockIdx.x * blockDim.x + threadIdx.x) >> 5;
    const int nw   = (gridDim.x * blockDim.x) >> 5;

    for (int n = warp; n < N_NODES; n += nw) {
        const int lo = g_off[n], hi = g_off[n + 1];
        float a0 = 0.f, a1 = 0.f, a2 = 0.f, a3 = 0.f;
        for (int ep = lo; ep < hi; ep++) {
            const uint32_t* mr = g_msg + (size_t)ep * 64;
            uint32_t u0 = __ldg(mr + lane);
            uint32_t u1 = __ldg(mr + 32 + lane);
            __half2 h0 = *reinterpret_cast<__half2*>(&u0);
            __half2 h1 = *reinterpret_cast<__half2*>(&u1);
            a0 += __low2float(h0); a1 += __high2float(h0);
            a2 += __low2float(h1); a3 += __high2float(h1);
        }
        *reinterpret_cast<float2*>(g_agg + (size_t)n * H + 2 * lane) =
            make_float2(a0, a1);
        *reinterpret_cast<float2*>(g_agg + (size_t)n * H + 64 + 2 * lane) =
            make_float2(a2, a3);
    }
}

// ======================= fused node kernel =================================
// h = relu( relu([h | agg*inv] @ W1 + b1) @ W2 + b2 + h )
// Single-pass fp16; U register-resident; split cp.async staging (R12).

__global__ void __launch_bounds__(256, 1)
node_kernel(const float* __restrict__ W1, const float* __restrict__ b1,
            const float* __restrict__ W2, const float* __restrict__ b2) {
    extern __shared__ char smem[];
    const uint32_t sb = smem_u32(smem);
    float* s_b1 = reinterpret_cast<float*>(smem + NB_B);
    float* s_b2 = s_b1 + 128;
    float* s_raw = reinterpret_cast<float*>(smem + NB_RAW);

    const int tid  = threadIdx.x;
    const int wid  = tid >> 5;
    const int lane = tid & 31;

    stage_w_f16(smem, W1, NB_W1, 2 * H, PADW);
    stage_w_f16(smem, W2, NB_W2, H, PAD);
    if (tid < 128) {
        s_b1[tid] = b1[tid];
        s_b2[tid] = b2[tid];
    }
    __syncthreads();

    const int m0 = wid * 16;
    const int rq = lane >> 2;
    const int cp = (lane & 3) * 2;
    const uint32_t aOffLane = ((uint32_t)(m0 + (lane & 15)) * PAD + 8u * (lane >> 4)) * 2u;
    const uint32_t b1OffLane = ((uint32_t)((lane & 7) + 8 * ((lane >> 3) & 1)) * PADW +
                                8u * (lane >> 4)) * 2u;
    const uint32_t b2OffLane = ((uint32_t)((lane & 7) + 8 * ((lane >> 3) & 1)) * PAD +
                                8u * (lane >> 4)) * 2u;

    const int NTN = (N_NODES + 127) / 128;  // 391

    for (int t = blockIdx.x; t < NTN; t += gridDim.x) {
        // ---- issue h staging (retires first)
        for (int i = tid; i < 128 * 16; i += 256) {
            const int r = i >> 4, wq = (i & 15) << 2;
            const int node = t * 128 + r;
            if (node < N_NODES)
                CP_ASYNC16(sb + NB_A + (uint32_t)(r * PAD + 2 * wq) * 2u,
                           g_hp + (size_t)node * 64 + wq);
        }
        CP_COMMIT();
        // ---- issue agg staging into raw buffer (overlaps GEMM1-phase0)
        for (int i = tid; i < 128 * 32; i += 256) {
            const int r = i >> 5, c4 = (i & 31) << 2;
            const int node = t * 128 + r;
            if (node < N_NODES)
                CP_ASYNC16(sb + NB_RAW + (uint32_t)(r * 128 + c4) * 4u,
                           g_agg + (size_t)node * H + c4);
        }
        CP_COMMIT();

        float acc[16][4];
#pragma unroll
        for (int j = 0; j < 16; j++) {
            const int n = j * 8 + cp;
            acc[j][0] = s_b1[n]; acc[j][1] = s_b1[n + 1];
            acc[j][2] = s_b1[n]; acc[j][3] = s_b1[n + 1];
        }

        CP_WAIT1();
        __syncthreads();

        // ---- GEMM1 phase 0 (A = h)
#pragma unroll
        for (int ks = 0; ks < 8; ks++) {
            const uint32_t k0a = (uint32_t)ks * 32u;
            uint32_t ah[4];
            ldsm_x4(ah, sb + NB_A + aOffLane + k0a);
#pragma unroll
            for (int jj = 0; jj < 8; jj++) {
                const uint32_t bo = b1OffLane + k0a + (uint32_t)jj * (16 * PADW * 2);
                uint32_t bh[4];
                ldsm_x4(bh, sb + NB_W1 + bo);
                mma16816(acc[2 * jj],     ah, bh[0], bh[2]);
                mma16816(acc[2 * jj + 1], ah, bh[1], bh[3]);
            }
        }

        CP_WAIT0();
        __syncthreads();

        // ---- convert raw agg -> scaled fp16 A
        {
            const int r = tid >> 1;
            const int hc = (tid & 1) * 64;
            const int node = t * 128 + r;
            const bool v = (node < N_NODES);
            const float sc = v ? __ldg(&g_inv[node]) : 0.f;
            const float* rp = s_raw + r * 128 + hc;
            char* dh = smem + NB_A + (r * PAD + hc) * 2;
#pragma unroll
            for (int p = 0; p < 8; p++) {
                float4 v0 = *reinterpret_cast<const float4*>(rp + 8 * p);
                float4 v1 = *reinterpret_cast<const float4*>(rp + 8 * p + 4);
                uint4 wh = make_uint4(packh2(v0.x * sc, v0.y * sc),
                                      packh2(v0.z * sc, v0.w * sc),
                                      packh2(v1.x * sc, v1.y * sc),
                                      packh2(v1.z * sc, v1.w * sc));
                *reinterpret_cast<uint4*>(dh + p * 16) = wh;
            }
        }
        __syncthreads();

        // ---- GEMM1 phase 1 (A = agg*inv)
#pragma unroll
        for (int ks = 0; ks < 8; ks++) {
            const uint32_t k0a = (uint32_t)ks * 32u;
            uint32_t ah[4];
            ldsm_x4(ah, sb + NB_A + aOffLane + k0a);
#pragma unroll
            for (int jj = 0; jj < 8; jj++) {
                const uint32_t bo = b1OffLane + 256u + k0a + (uint32_t)jj * (16 * PADW * 2);
                uint32_t bh[4];
                ldsm_x4(bh, sb + NB_W1 + bo);
                mma16816(acc[2 * jj],     ah, bh[0], bh[2]);
                mma16816(acc[2 * jj + 1], ah, bh[1], bh[3]);
            }
        }
        __syncthreads();

        // ---- U = relu(acc) -> fp16 A-frags in registers
        uint32_t a2[8][4];
#pragma unroll
        for (int gg = 0; gg < 8; gg++) {
            a2[gg][0] = packh2(fmaxf(acc[2 * gg][0], 0.f),     fmaxf(acc[2 * gg][1], 0.f));
            a2[gg][1] = packh2(fmaxf(acc[2 * gg][2], 0.f),     fmaxf(acc[2 * gg][3], 0.f));
            a2[gg][2] = packh2(fmaxf(acc[2 * gg + 1][0], 0.f), fmaxf(acc[2 * gg + 1][1], 0.f));
            a2[gg][3] = packh2(fmaxf(acc[2 * gg + 1][2], 0.f), fmaxf(acc[2 * gg + 1][3], 0.f));
        }

#pragma unroll
        for (int j = 0; j < 16; j++) {
            const int n = j * 8 + cp;
            acc[j][0] = s_b2[n]; acc[j][1] = s_b2[n + 1];
            acc[j][2] = s_b2[n]; acc[j][3] = s_b2[n + 1];
        }

        // ---- GEMM2
#pragma unroll
        for (int ks = 0; ks < 8; ks++) {
            const uint32_t k0b = (uint32_t)ks * 32u;
#pragma unroll
            for (int jj = 0; jj < 8; jj++) {
                const uint32_t bo = b2OffLane + k0b + (uint32_t)jj * (16 * PAD * 2);
                uint32_t bh[4];
                ldsm_x4(bh, sb + NB_W2 + bo);
                mma16816(acc[2 * jj],     a2[ks], bh[0], bh[2]);
                mma16816(acc[2 * jj + 1], a2[ks], bh[1], bh[3]);
            }
        }

        // ---- epilogue: + h residual, relu, write g_h fp32 + g_hp hi plane
        {
            const int r0 = m0 + rq, r1 = r0 + 8;
            const int n0 = t * 128 + r0, n1 = t * 128 + r1;
#pragma unroll
            for (int j = 0; j < 16; j++) {
                const int n = j * 8 + cp;
                const int w = n >> 1;
                if (n0 < N_NODES) {
                    float2 h0 = *reinterpret_cast<const float2*>(g_h + (size_t)n0 * H + n);
                    float2 o0 = make_float2(fmaxf(acc[j][0] + h0.x, 0.f),
                                            fmaxf(acc[j][1] + h0.y, 0.f));
                    *reinterpret_cast<float2*>(g_h + (size_t)n0 * H + n) = o0;
                    g_hp[(size_t)n0 * 64 + w] = packh2(o0.x, o0.y);
                }
                if (n1 < N_NODES) {
                    float2 h1 = *reinterpret_cast<const float2*>(g_h + (size_t)n1 * H + n);
                    float2 o1 = make_float2(fmaxf(acc[j][2] + h1.x, 0.f),
                                            fmaxf(acc[j][3] + h1.y, 0.f));
                    *reinterpret_cast<float2*>(g_h + (size_t)n1 * H + n) = o1;
                    g_hp[(size_t)n1 * 64 + w] = packh2(o1.x, o1.y);
                }
            }
        }
        __syncthreads();
    }
}

// ======================= head ==============================================

__global__ void __launch_bounds__(256, 1)
head_kernel(const float* __restrict__ W1, const float* __restrict__ b1,
            const float* __restrict__ W2, const float* __restrict__ b2,
            float* __restrict__ out) {
    extern __shared__ float sm[];
    float* sW1 = sm;
    float* sW2 = sW1 + H * H;
    float* sH  = sW2 + H * N_OUT;

    for (int i = threadIdx.x; i < H * H; i += 256) sW1[i] = W1[i];
    for (int i = threadIdx.x; i < H * N_OUT; i += 256) sW2[i] = W2[i];

    const int lane = threadIdx.x & 31;
    const int w    = threadIdx.x >> 5;
    float b1v[4];
#pragma unroll
    for (int j = 0; j < 4; j++) b1v[j] = __ldg(&b1[lane * 4 + j]);
    const float b2v0 = __ldg(&b2[0]), b2v1 = __ldg(&b2[1]), b2v2 = __ldg(&b2[2]);
    __syncthreads();

    const int ntiles = (N_NODES + TN - 1) / TN;
    for (int t = blockIdx.x; t < ntiles; t += gridDim.x) {
        const int n0 = t * TN + w * 4;
#pragma unroll
        for (int i = 0; i < 4; i++) {
            int n = n0 + i;
            float4 hv = make_float4(0.f, 0.f, 0.f, 0.f);
            if (n < N_NODES)
                hv = *reinterpret_cast<const float4*>(g_h + (size_t)n * H + lane * 4);
            *reinterpret_cast<float4*>(sH + (w * 4 + i) * H + lane * 4) = hv;
        }
        __syncwarp();

        float acc[4][4];
#pragma unroll
        for (int i = 0; i < 4; i++) {
            acc[i][0] = b1v[0]; acc[i][1] = b1v[1];
            acc[i][2] = b1v[2]; acc[i][3] = b1v[3];
        }
#pragma unroll 1
        for (int kc = 0; kc < H; kc += 4) {
            float4 a4[4];
#pragma unroll
            for (int i = 0; i < 4; i++)
                a4[i] = *reinterpret_cast<const float4*>(sH + (w * 4 + i) * H + kc);
#pragma unroll
            for (int kk = 0; kk < 4; kk++) {
                float4 bv = *reinterpret_cast<const float4*>(sW1 + (kc + kk) * H + lane * 4);
#pragma unroll
                for (int i = 0; i < 4; i++) {
                    float a = (kk == 0) ? a4[i].x : (kk == 1) ? a4[i].y
                             : (kk == 2) ? a4[i].z : a4[i].w;
                    acc[i][0] = fmaf(a, bv.x, acc[i][0]);
                    acc[i][1] = fmaf(a, bv.y, acc[i][1]);
                    acc[i][2] = fmaf(a, bv.z, acc[i][2]);
                    acc[i][3] = fmaf(a, bv.w, acc[i][3]);
                }
            }
        }

#pragma unroll
        for (int i = 0; i < 4; i++) {
            float p0 = 0.f, p1 = 0.f, p2 = 0.f;
#pragma unroll
            for (int j = 0; j < 4; j++) {
                float o = fmaxf(acc[i][j], 0.f);
                int kk = lane * 4 + j;
                p0 = fmaf(o, sW2[kk * N_OUT + 0], p0);
                p1 = fmaf(o, sW2[kk * N_OUT + 1], p1);
                p2 = fmaf(o, sW2[kk * N_OUT + 2], p2);
            }
#pragma unroll
            for (int off = 16; off > 0; off >>= 1) {
                p0 += __shfl_xor_sync(0xffffffffu, p0, off);
                p1 += __shfl_xor_sync(0xffffffffu, p1, off);
                p2 += __shfl_xor_sync(0xffffffffu, p2, off);
            }
            int n = n0 + i;
            if (lane == 0 && n < N_NODES) {
                out[(size_t)n * N_OUT + 0] = fmaxf(p0 + b2v0, 0.f);
                out[(size_t)n * N_OUT + 1] = fmaxf(p1 + b2v1, 0.f);
                out[(size_t)n * N_OUT + 2] = fmaxf(p2 + b2v2, 0.f);
            }
        }
        __syncwarp();
    }
}

// ======================= launch ============================================

extern "C" void kernel_launch(void* const* d_in, const int* in_sizes, int n_in,
                              void* d_out, int out_size) {
    const float* x       = (const float*)d_in[0];
    const int*   ei      = (const int*)d_in[1];
    const float* ea      = (const float*)d_in[2];
    const float* lin_w   = (const float*)d_in[3];
    const float* lin_b   = (const float*)d_in[4];
    const float* msg_w1  = (const float*)d_in[5];
    const float* msg_b1  = (const float*)d_in[6];
    const float* msg_w2  = (const float*)d_in[7];
    const float* msg_b2  = (const float*)d_in[8];
    const float* upd_w1  = (const float*)d_in[9];
    const float* upd_b1  = (const float*)d_in[10];
    const float* upd_w2  = (const float*)d_in[11];
    const float* upd_b2  = (const float*)d_in[12];
    const float* head_w1 = (const float*)d_in[13];
    const float* head_b1 = (const float*)d_in[14];
    const float* head_w2 = (const float*)d_in[15];
    const float* head_b2 = (const float*)d_in[16];
    float* out = (float*)d_out;

    const int* src = ei;
    const int* dst = ei + N_EDGES;

    int sm_count = 148;
    cudaDeviceGetAttribute(&sm_count, cudaDevAttrMultiProcessorCount, 0);

    const size_t smHd = (size_t)(H * H + H * N_OUT + TN * H) * sizeof(float);
    cudaFuncSetAttribute(edge_kernel, cudaFuncAttributeMaxDynamicSharedMemorySize, SM_EDGE_TOTAL);
    cudaFuncSetAttribute(node_kernel, cudaFuncAttributeMaxDynamicSharedMemorySize, NB_TOTAL);
    cudaFuncSetAttribute(head_kernel, cudaFuncAttributeMaxDynamicSharedMemorySize, (int)smHd);

    zero_cnt_kernel<<<(N_NODES + 255) / 256, 256>>>();
    deg_kernel<<<(N_EDGES + 255) / 256, 256>>>(dst);
    scan_kernel<<<1, 1024>>>();                       // g_off, g_cnt from degrees
    prep_kernel<<<1024, 256>>>(ea);                   // g_inv <- 1/deg, pack ea
    scatter_kernel<<<(N_EDGES + 255) / 256, 256>>>(src, dst);  // g_ssrc, g_sperm
    lin_in_kernel<<<N_NODES, H>>>(x, lin_w, lin_b);

    for (int l = 0; l < N_LAYERS; l++) {
        edge_kernel<<<sm_count, 256, SM_EDGE_TOTAL>>>(
            msg_w1 + (size_t)l * (H + ED) * H, msg_b1 + (size_t)l * H,
            msg_w2 + (size_t)l * H * H, msg_b2 + (size_t)l * H);
        agg_kernel<<<4 * sm_count, 256>>>();
        node_kernel<<<sm_count, 256, NB_TOTAL>>>(
            upd_w1 + (size_t)l * 2 * H * H, upd_b1 + (size_t)l * H,
            upd_w2 + (size_t)l * H * H, upd_b2 + (size_t)l * H);
    }

    head_kernel<<<2 * sm_count, 256, smHd>>>(head_w1, head_b1, head_w2, head_b2, out);
}

// round 16
// speedup vs baseline: 1.2006x; 1.2006x over previous
#include <cuda_runtime.h>
#include <cuda_fp16.h>
#include <cstdint>
#include <cstddef>

// ---------------------------------------------------------------------------
// MeshGNN: N=50000, E=600000, IN=16, ED=4, H=128, L=4, OUT=3
// Round 15: R12 config (best: 1328us) + edge kernel widened to 3 groups
// (384 thr, 12 warps/SM) for cross-group phase overlap (gather / MMA /
// atomic-drain). Node kernel: R12 split-cp.async overlap version.
// ---------------------------------------------------------------------------

#define N_NODES 50000
#define N_EDGES 600000
#define H 128
#define IN_F 16
#define ED 4
#define N_LAYERS 4
#define N_OUT 3
#define TN 32

#define PAD  136   // node A / W2 k stride (elements)
#define PADW 264   // node W1 (K=256) stride
#define EPAD 152   // edge kernel stride: 128 ch + 16 ea block + 8 slack

#define A_BUF  19456   // 64 * EPAD * 2
#define NGRP   3       // edge kernel groups (of 4 warps each)

// ---- edge kernel smem map (bytes)
#define SM_B1   0
#define SM_B2   512
#define SM_DST  1024     // + gb*256, gb in [0,6)
#define SM_W1   4096     // 38912 (incl. ea rows at k=128..143)
#define SM_W2   43008    // 38912
#define SM_A    81920    // + gb*19456, 6 bufs
#define SM_EDGE_TOTAL 198656

// ---- fused node smem map
#define NB_B    0        // b1[128] b2[128] = 1024
#define NB_W1   1024     // 128*PADW*2 = 67584
#define NB_W2   68608    // 128*PAD*2  = 34816
#define NB_A    103424   // 128*PAD*2  = 34816
#define NB_RAW  138240   // 128*128*4  = 65536 (raw fp32 agg tile)
#define NB_TOTAL 203776

__device__ float g_h[(size_t)N_NODES * H];
__device__ float g_agg[(size_t)N_NODES * H];
__device__ float g_inv[N_NODES];
__device__ uint32_t g_hp[(size_t)N_NODES * 64];    // packed fp16 h (hi plane only)
__device__ uint32_t g_eap[(size_t)N_EDGES * 8];    // fp16 ea block (4 real + 12 zero)

// ======================= helpers ==========================================

__device__ __forceinline__ uint32_t smem_u32(const void* p) {
    uint32_t a;
    asm("{ .reg .u64 t; cvta.to.shared.u64 t, %1; cvt.u32.u64 %0, t; }"
        : "=r"(a) : "l"(p));
    return a;
}

__device__ __forceinline__ void ldsm_x4(uint32_t* r, uint32_t addr) {
    asm volatile("ldmatrix.sync.aligned.m8n8.x4.shared.b16 {%0,%1,%2,%3}, [%4];"
                 : "=r"(r[0]), "=r"(r[1]), "=r"(r[2]), "=r"(r[3]) : "r"(addr));
}

__device__ __forceinline__ void mma16816(float* c, const uint32_t* a,
                                         uint32_t b0, uint32_t b1) {
    asm volatile(
        "mma.sync.aligned.m16n8k16.row.col.f32.f16.f16.f32 "
        "{%0,%1,%2,%3}, {%4,%5,%6,%7}, {%8,%9}, {%0,%1,%2,%3};"
        : "+f"(c[0]), "+f"(c[1]), "+f"(c[2]), "+f"(c[3])
        : "r"(a[0]), "r"(a[1]), "r"(a[2]), "r"(a[3]), "r"(b0), "r"(b1));
}

__device__ __forceinline__ uint32_t packh2(float x, float y) {
    __half2 h = __floats2half2_rn(x, y);
    return *reinterpret_cast<uint32_t*>(&h);
}

#define GROUP_BAR(gid) \
    asm volatile("bar.sync %0, %1;" :: "r"(1 + (gid)), "r"(128) : "memory")

#define CP_ASYNC16(dst, src) \
    asm volatile("cp.async.ca.shared.global [%0], [%1], 16;" :: "r"(dst), "l"(src) : "memory")
#define CP_ASYNC4(dst, src) \
    asm volatile("cp.async.ca.shared.global [%0], [%1], 4;" :: "r"(dst), "l"(src) : "memory")
#define CP_COMMIT() asm volatile("cp.async.commit_group;" ::: "memory")
#define CP_WAIT0()  asm volatile("cp.async.wait_group 0;" ::: "memory")
#define CP_WAIT1()  asm volatile("cp.async.wait_group 1;" ::: "memory")

// ======================= small helper kernels ==============================

__global__ void zero_cnt_kernel() {
    int i = blockIdx.x * blockDim.x + threadIdx.x;
    if (i < N_NODES) g_inv[i] = 0.f;
}

__global__ void deg_kernel(const int* __restrict__ dst) {
    int e = blockIdx.x * blockDim.x + threadIdx.x;
    if (e < N_EDGES) atomicAdd(&g_inv[dst[e]], 1.0f);
}

// fused: inv (after deg), zero g_agg, pack ea
__global__ void prep_kernel(const float* __restrict__ ea) {
    const size_t gtid = (size_t)blockIdx.x * blockDim.x + threadIdx.x;
    const size_t gsz  = (size_t)gridDim.x * blockDim.x;
    for (size_t i = gtid; i < N_NODES; i += gsz)
        g_inv[i] = 1.0f / fmaxf(g_inv[i], 1.0f);
    const float4 z = make_float4(0.f, 0.f, 0.f, 0.f);
    for (size_t i = gtid; i < (size_t)N_NODES * H / 4; i += gsz)
        reinterpret_cast<float4*>(g_agg)[i] = z;
    for (size_t e = gtid; e < N_EDGES; e += gsz) {
        float4 a = *reinterpret_cast<const float4*>(ea + e * 4);
        uint4* p = reinterpret_cast<uint4*>(g_eap + e * 8);
        p[0] = make_uint4(packh2(a.x, a.y), packh2(a.z, a.w), 0u, 0u);
        p[1] = make_uint4(0u, 0u, 0u, 0u);
    }
}

// h = relu(x @ W + b); writes fp32 g_h + packed fp16 hi plane g_hp
__global__ void lin_in_kernel(const float* __restrict__ x,
                              const float* __restrict__ W,
                              const float* __restrict__ b) {
    __shared__ float sx[IN_F];
    __shared__ float sh[H];
    int n = blockIdx.x;
    if (threadIdx.x < IN_F) sx[threadIdx.x] = x[(size_t)n * IN_F + threadIdx.x];
    __syncthreads();
    int c = threadIdx.x;
    float acc = __ldg(&b[c]);
#pragma unroll
    for (int k = 0; k < IN_F; k++)
        acc = fmaf(sx[k], __ldg(&W[k * H + c]), acc);
    float v = fmaxf(acc, 0.f);
    g_h[(size_t)n * H + c] = v;
    sh[c] = v;
    __syncthreads();
    if (threadIdx.x < 64) {
        int w = threadIdx.x;
        g_hp[(size_t)n * 64 + w] = packh2(sh[2 * w], sh[2 * w + 1]);
    }
}

// stage W[k][n] fp32 transposed into WT[n][k] fp16, stride pad
__device__ __forceinline__ void stage_w_f16(char* smem, const float* __restrict__ W,
                                            int off, int kdim, int pad) {
    for (int idx = threadIdx.x; idx < kdim * H; idx += blockDim.x) {
        int k = idx >> 7, n = idx & 127;
        *reinterpret_cast<__half*>(smem + off + (n * pad + k) * 2) = __float2half(W[idx]);
    }
}

// ======================= edge kernel =======================================
// 384 thr = 3 groups x 4 warps; 64-edge tiles per group, double-buffered
// cp.async A, ea folded as k=128..143; single-pass fp16; float2 scatter.
// 3 groups/SMSP give cross-phase overlap (gather / MMA / atomic drain).

__device__ __forceinline__ void edge_prefetch(
    uint32_t sb, int gb, int e0, int srcval, int ltid,
    const int* __restrict__ dst) {
    const int r  = ltid >> 1;
    const int hc = (ltid & 1) * 64;
    const uint32_t* sp = g_hp + (size_t)srcval * 64 + (ltid & 1) * 32;
    uint32_t dh = sb + SM_A + (uint32_t)gb * (uint32_t)A_BUF +
                  (uint32_t)(r * EPAD + hc) * 2u;
#pragma unroll
    for (int p = 0; p < 8; p++) CP_ASYNC16(dh + 16u * p, sp + 4 * p);
    if (ltid < 64) {
        const int e = e0 + ltid;
        uint32_t de = sb + SM_A + (uint32_t)gb * (uint32_t)A_BUF +
                      (uint32_t)(ltid * EPAD + 128) * 2u;
        const uint32_t* ep = g_eap + (size_t)e * 8;
        CP_ASYNC16(de, ep);
        CP_ASYNC16(de + 16u, ep + 4);
        CP_ASYNC4(sb + SM_DST + (uint32_t)gb * 256u + (uint32_t)ltid * 4u, dst + e);
    }
}

__global__ void __launch_bounds__(128 * NGRP, 1)
edge_kernel(const int* __restrict__ src, const int* __restrict__ dst,
            const float* __restrict__ W1, const float* __restrict__ b1,
            const float* __restrict__ W2, const float* __restrict__ b2) {
    extern __shared__ char smem[];
    const uint32_t sb = smem_u32(smem);
    float* s_b1 = reinterpret_cast<float*>(smem + SM_B1);
    float* s_b2 = reinterpret_cast<float*>(smem + SM_B2);

    const int tid  = threadIdx.x;
    const int wid  = tid >> 5;
    const int lane = tid & 31;
    const int g    = wid >> 2;       // group 0..NGRP-1
    const int lw   = wid & 3;
    const int ltid = tid & 127;

    for (int idx = tid; idx < 144 * 128; idx += 128 * NGRP) {
        int k = idx >> 7, n = idx & 127;
        float v = (k < 128) ? W1[k * H + n]
                : (k < 132) ? W1[(H + k - 128) * H + n] : 0.f;
        *reinterpret_cast<__half*>(smem + SM_W1 + (n * EPAD + k) * 2) = __float2half(v);
    }
    for (int idx = tid; idx < 128 * 128; idx += 128 * NGRP) {
        int k = idx >> 7, n = idx & 127;
        *reinterpret_cast<__half*>(smem + SM_W2 + (n * EPAD + k) * 2) =
            __float2half(W2[idx]);
    }
    if (tid < 128) {
        s_b1[tid] = b1[tid];
        s_b2[tid] = b2[tid];
    }
    __syncthreads();

    const int m0 = lw * 16;
    const int rq = lane >> 2;
    const int cp = (lane & 3) * 2;
    const uint32_t aOffLane = ((uint32_t)(m0 + (lane & 15)) * EPAD + 8u * (lane >> 4)) * 2u;
    const uint32_t bOffLane = ((uint32_t)((lane & 7) + 8 * ((lane >> 3) & 1)) * EPAD +
                               8u * (lane >> 4)) * 2u;

    const int NT = N_EDGES / 64;  // 9375
    const int stride = gridDim.x * NGRP;
    int t = blockIdx.x * NGRP + g;
    int buf = 0;
    int nsrc = 0;

    if (t < NT) {
        nsrc = __ldg(&src[t * 64 + (ltid >> 1)]);
        edge_prefetch(sb, g * 2, t * 64, nsrc, ltid, dst);
        CP_COMMIT();
        int t2 = t + stride;
        nsrc = (t2 < NT) ? __ldg(&src[t2 * 64 + (ltid >> 1)]) : 0;
    }

    for (; t < NT; t += stride) {
        CP_WAIT0();
        GROUP_BAR(g);

        const int tn = t + stride;
        if (tn < NT) {
            edge_prefetch(sb, g * 2 + (buf ^ 1), tn * 64, nsrc, ltid, dst);
            CP_COMMIT();
            const int tnn = tn + stride;
            if (tnn < NT) nsrc = __ldg(&src[tnn * 64 + (ltid >> 1)]);
        }

        const uint32_t bA = sb + SM_A + (uint32_t)(g * 2 + buf) * (uint32_t)A_BUF;
        int* s_dst = reinterpret_cast<int*>(smem + SM_DST + (g * 2 + buf) * 256);

        float acc[16][4];
#pragma unroll
        for (int j = 0; j < 16; j++) {
            const int n = j * 8 + cp;
            acc[j][0] = s_b1[n]; acc[j][1] = s_b1[n + 1];
            acc[j][2] = s_b1[n]; acc[j][3] = s_b1[n + 1];
        }

        // GEMM1: 9 uniform k-steps (k-step 8 = ea @ W1b)
#pragma unroll
        for (int ks = 0; ks < 9; ks++) {
            const uint32_t k0b = (uint32_t)ks * 32u;
            uint32_t ah[4];
            ldsm_x4(ah, bA + aOffLane + k0b);
#pragma unroll
            for (int jj = 0; jj < 8; jj++) {
                const uint32_t bo = bOffLane + k0b + (uint32_t)jj * (16 * EPAD * 2);
                uint32_t bh[4];
                ldsm_x4(bh, sb + SM_W1 + bo);
                mma16816(acc[2 * jj],     ah, bh[0], bh[2]);
                mma16816(acc[2 * jj + 1], ah, bh[1], bh[3]);
            }
        }

        // relu + fp16 re-pack (C frags -> A frags)
        uint32_t a2[8][4];
#pragma unroll
        for (int gg = 0; gg < 8; gg++) {
            a2[gg][0] = packh2(fmaxf(acc[2 * gg][0], 0.f),     fmaxf(acc[2 * gg][1], 0.f));
            a2[gg][1] = packh2(fmaxf(acc[2 * gg][2], 0.f),     fmaxf(acc[2 * gg][3], 0.f));
            a2[gg][2] = packh2(fmaxf(acc[2 * gg + 1][0], 0.f), fmaxf(acc[2 * gg + 1][1], 0.f));
            a2[gg][3] = packh2(fmaxf(acc[2 * gg + 1][2], 0.f), fmaxf(acc[2 * gg + 1][3], 0.f));
        }

#pragma unroll
        for (int j = 0; j < 16; j++) {
            const int n = j * 8 + cp;
            acc[j][0] = s_b2[n]; acc[j][1] = s_b2[n + 1];
            acc[j][2] = s_b2[n]; acc[j][3] = s_b2[n + 1];
        }

        // GEMM2
#pragma unroll
        for (int ks = 0; ks < 8; ks++) {
            const uint32_t k0b = (uint32_t)ks * 32u;
#pragma unroll
            for (int jj = 0; jj < 8; jj++) {
                const uint32_t bo = bOffLane + k0b + (uint32_t)jj * (16 * EPAD * 2);
                uint32_t bh[4];
                ldsm_x4(bh, sb + SM_W2 + bo);
                mma16816(acc[2 * jj],     a2[ks], bh[0], bh[2]);
                mma16816(acc[2 * jj + 1], a2[ks], bh[1], bh[3]);
            }
        }

        // relu + float2 atomic scatter (proven form)
        {
            const int r0 = m0 + rq, r1 = r0 + 8;
            float* p0 = g_agg + (size_t)s_dst[r0] * H;
            float* p1 = g_agg + (size_t)s_dst[r1] * H;
#pragma unroll
            for (int j = 0; j < 16; j++) {
                const int n = j * 8 + cp;
                atomicAdd(reinterpret_cast<float2*>(p0 + n),
                          make_float2(fmaxf(acc[j][0], 0.f), fmaxf(acc[j][1], 0.f)));
                atomicAdd(reinterpret_cast<float2*>(p1 + n),
                          make_float2(fmaxf(acc[j][2], 0.f), fmaxf(acc[j][3], 0.f)));
            }
        }
        buf ^= 1;
    }
}

// ======================= fused node kernel (R12) ===========================
// h = relu( relu([h | agg*inv] @ W1 + b1) @ W2 + b2 + h )
// Single-pass fp16; U register-resident; split cp.async staging; conversion
// phase also zeroes g_agg for the next layer.

__global__ void __launch_bounds__(256, 1)
node_kernel(const float* __restrict__ W1, const float* __restrict__ b1,
            const float* __restrict__ W2, const float* __restrict__ b2) {
    extern __shared__ char smem[];
    const uint32_t sb = smem_u32(smem);
    float* s_b1 = reinterpret_cast<float*>(smem + NB_B);
    float* s_b2 = s_b1 + 128;
    float* s_raw = reinterpret_cast<float*>(smem + NB_RAW);

    const int tid  = threadIdx.x;
    const int wid  = tid >> 5;
    const int lane = tid & 31;

    stage_w_f16(smem, W1, NB_W1, 2 * H, PADW);
    stage_w_f16(smem, W2, NB_W2, H, PAD);
    if (tid < 128) {
        s_b1[tid] = b1[tid];
        s_b2[tid] = b2[tid];
    }
    __syncthreads();

    const int m0 = wid * 16;
    const int rq = lane >> 2;
    const int cp = (lane & 3) * 2;
    const uint32_t aOffLane = ((uint32_t)(m0 + (lane & 15)) * PAD + 8u * (lane >> 4)) * 2u;
    const uint32_t b1OffLane = ((uint32_t)((lane & 7) + 8 * ((lane >> 3) & 1)) * PADW +
                                8u * (lane >> 4)) * 2u;
    const uint32_t b2OffLane = ((uint32_t)((lane & 7) + 8 * ((lane >> 3) & 1)) * PAD +
                                8u * (lane >> 4)) * 2u;

    const int NTN = (N_NODES + 127) / 128;  // 391

    for (int t = blockIdx.x; t < NTN; t += gridDim.x) {
        // ---- issue h staging (retires first)
        for (int i = tid; i < 128 * 16; i += 256) {
            const int r = i >> 4, wq = (i & 15) << 2;
            const int node = t * 128 + r;
            if (node < N_NODES)
                CP_ASYNC16(sb + NB_A + (uint32_t)(r * PAD + 2 * wq) * 2u,
                           g_hp + (size_t)node * 64 + wq);
        }
        CP_COMMIT();
        // ---- issue agg staging into raw buffer (overlaps GEMM1-phase0)
        for (int i = tid; i < 128 * 32; i += 256) {
            const int r = i >> 5, c4 = (i & 31) << 2;
            const int node = t * 128 + r;
            if (node < N_NODES)
                CP_ASYNC16(sb + NB_RAW + (uint32_t)(r * 128 + c4) * 4u,
                           g_agg + (size_t)node * H + c4);
        }
        CP_COMMIT();

        float acc[16][4];
#pragma unroll
        for (int j = 0; j < 16; j++) {
            const int n = j * 8 + cp;
            acc[j][0] = s_b1[n]; acc[j][1] = s_b1[n + 1];
            acc[j][2] = s_b1[n]; acc[j][3] = s_b1[n + 1];
        }

        CP_WAIT1();          // h tile ready (agg may still be in flight)
        __syncthreads();

        // ---- GEMM1 phase 0 (A = h)
#pragma unroll
        for (int ks = 0; ks < 8; ks++) {
            const uint32_t k0a = (uint32_t)ks * 32u;
            uint32_t ah[4];
            ldsm_x4(ah, sb + NB_A + aOffLane + k0a);
#pragma unroll
            for (int jj = 0; jj < 8; jj++) {
                const uint32_t bo = b1OffLane + k0a + (uint32_t)jj * (16 * PADW * 2);
                uint32_t bh[4];
                ldsm_x4(bh, sb + NB_W1 + bo);
                mma16816(acc[2 * jj],     ah, bh[0], bh[2]);
                mma16816(acc[2 * jj + 1], ah, bh[1], bh[3]);
            }
        }

        CP_WAIT0();          // agg raw tile ready
        __syncthreads();     // all warps done reading A(h)

        // ---- convert raw agg -> scaled fp16 A; zero g_agg rows
        {
            const int r = tid >> 1;
            const int hc = (tid & 1) * 64;
            const int node = t * 128 + r;
            const bool v = (node < N_NODES);
            const float sc = v ? __ldg(&g_inv[node]) : 0.f;
            const float* rp = s_raw + r * 128 + hc;
            char* dh = smem + NB_A + (r * PAD + hc) * 2;
#pragma unroll
            for (int p = 0; p < 8; p++) {
                float4 v0 = *reinterpret_cast<const float4*>(rp + 8 * p);
                float4 v1 = *reinterpret_cast<const float4*>(rp + 8 * p + 4);
                uint4 wh = make_uint4(packh2(v0.x * sc, v0.y * sc),
                                      packh2(v0.z * sc, v0.w * sc),
                                      packh2(v1.x * sc, v1.y * sc),
                                      packh2(v1.z * sc, v1.w * sc));
                *reinterpret_cast<uint4*>(dh + p * 16) = wh;
            }
            if (v) {
                float4 z = make_float4(0.f, 0.f, 0.f, 0.f);
                float* zp = g_agg + (size_t)node * H + hc;
#pragma unroll
                for (int p = 0; p < 16; p++)
                    reinterpret_cast<float4*>(zp)[p] = z;
            }
        }
        __syncthreads();

        // ---- GEMM1 phase 1 (A = agg*inv)
#pragma unroll
        for (int ks = 0; ks < 8; ks++) {
            const uint32_t k0a = (uint32_t)ks * 32u;
            uint32_t ah[4];
            ldsm_x4(ah, sb + NB_A + aOffLane + k0a);
#pragma unroll
            for (int jj = 0; jj < 8; jj++) {
                const uint32_t bo = b1OffLane + 256u + k0a + (uint32_t)jj * (16 * PADW * 2);
                uint32_t bh[4];
                ldsm_x4(bh, sb + NB_W1 + bo);
                mma16816(acc[2 * jj],     ah, bh[0], bh[2]);
                mma16816(acc[2 * jj + 1], ah, bh[1], bh[3]);
            }
        }
        __syncthreads();     // A reads done before next tile's cp.async

        // ---- U = relu(acc) -> fp16 A-frags in registers
        uint32_t a2[8][4];
#pragma unroll
        for (int gg = 0; gg < 8; gg++) {
            a2[gg][0] = packh2(fmaxf(acc[2 * gg][0], 0.f),     fmaxf(acc[2 * gg][1], 0.f));
            a2[gg][1] = packh2(fmaxf(acc[2 * gg][2], 0.f),     fmaxf(acc[2 * gg][3], 0.f));
            a2[gg][2] = packh2(fmaxf(acc[2 * gg + 1][0], 0.f), fmaxf(acc[2 * gg + 1][1], 0.f));
            a2[gg][3] = packh2(fmaxf(acc[2 * gg + 1][2], 0.f), fmaxf(acc[2 * gg + 1][3], 0.f));
        }

#pragma unroll
        for (int j = 0; j < 16; j++) {
            const int n = j * 8 + cp;
            acc[j][0] = s_b2[n]; acc[j][1] = s_b2[n + 1];
            acc[j][2] = s_b2[n]; acc[j][3] = s_b2[n + 1];
        }

        // ---- GEMM2: u2 = U @ W2 + b2
#pragma unroll
        for (int ks = 0; ks < 8; ks++) {
            const uint32_t k0b = (uint32_t)ks * 32u;
#pragma unroll
            for (int jj = 0; jj < 8; jj++) {
                const uint32_t bo = b2OffLane + k0b + (uint32_t)jj * (16 * PAD * 2);
                uint32_t bh[4];
                ldsm_x4(bh, sb + NB_W2 + bo);
                mma16816(acc[2 * jj],     a2[ks], bh[0], bh[2]);
                mma16816(acc[2 * jj + 1], a2[ks], bh[1], bh[3]);
            }
        }

        // ---- epilogue: + h residual, relu, write g_h fp32 + g_hp hi plane
        {
            const int r0 = m0 + rq, r1 = r0 + 8;
            const int n0 = t * 128 + r0, n1 = t * 128 + r1;
#pragma unroll
            for (int j = 0; j < 16; j++) {
                const int n = j * 8 + cp;
                const int w = n >> 1;
                if (n0 < N_NODES) {
                    float2 h0 = *reinterpret_cast<const float2*>(g_h + (size_t)n0 * H + n);
                    float2 o0 = make_float2(fmaxf(acc[j][0] + h0.x, 0.f),
                                            fmaxf(acc[j][1] + h0.y, 0.f));
                    *reinterpret_cast<float2*>(g_h + (size_t)n0 * H + n) = o0;
                    g_hp[(size_t)n0 * 64 + w] = packh2(o0.x, o0.y);
                }
                if (n1 < N_NODES) {
                    float2 h1 = *reinterpret_cast<const float2*>(g_h + (size_t)n1 * H + n);
                    float2 o1 = make_float2(fmaxf(acc[j][2] + h1.x, 0.f),
                                            fmaxf(acc[j][3] + h1.y, 0.f));
                    *reinterpret_cast<float2*>(g_h + (size_t)n1 * H + n) = o1;
                    g_hp[(size_t)n1 * 64 + w] = packh2(o1.x, o1.y);
                }
            }
        }
        __syncthreads();
    }
}

// ======================= head ==============================================

__global__ void __launch_bounds__(256, 1)
head_kernel(const float* __restrict__ W1, const float* __restrict__ b1,
            const float* __restrict__ W2, const float* __restrict__ b2,
            float* __restrict__ out) {
    extern __shared__ float sm[];
    float* sW1 = sm;
    float* sW2 = sW1 + H * H;
    float* sH  = sW2 + H * N_OUT;

    for (int i = threadIdx.x; i < H * H; i += 256) sW1[i] = W1[i];
    for (int i = threadIdx.x; i < H * N_OUT; i += 256) sW2[i] = W2[i];

    const int lane = threadIdx.x & 31;
    const int w    = threadIdx.x >> 5;
    float b1v[4];
#pragma unroll
    for (int j = 0; j < 4; j++) b1v[j] = __ldg(&b1[lane * 4 + j]);
    const float b2v0 = __ldg(&b2[0]), b2v1 = __ldg(&b2[1]), b2v2 = __ldg(&b2[2]);
    __syncthreads();

    const int ntiles = (N_NODES + TN - 1) / TN;
    for (int t = blockIdx.x; t < ntiles; t += gridDim.x) {
        const int n0 = t * TN + w * 4;
#pragma unroll
        for (int i = 0; i < 4; i++) {
            int n = n0 + i;
            float4 hv = make_float4(0.f, 0.f, 0.f, 0.f);
            if (n < N_NODES)
                hv = *reinterpret_cast<const float4*>(g_h + (size_t)n * H + lane * 4);
            *reinterpret_cast<float4*>(sH + (w * 4 + i) * H + lane * 4) = hv;
        }
        __syncwarp();

        float acc[4][4];
#pragma unroll
        for (int i = 0; i < 4; i++) {
            acc[i][0] = b1v[0]; acc[i][1] = b1v[1];
            acc[i][2] = b1v[2]; acc[i][3] = b1v[3];
        }
#pragma unroll 1
        for (int kc = 0; kc < H; kc += 4) {
            float4 a4[4];
#pragma unroll
            for (int i = 0; i < 4; i++)
                a4[i] = *reinterpret_cast<const float4*>(sH + (w * 4 + i) * H + kc);
#pragma unroll
            for (int kk = 0; kk < 4; kk++) {
                float4 bv = *reinterpret_cast<const float4*>(sW1 + (kc + kk) * H + lane * 4);
#pragma unroll
                for (int i = 0; i < 4; i++) {
                    float a = (kk == 0) ? a4[i].x : (kk == 1) ? a4[i].y
                             : (kk == 2) ? a4[i].z : a4[i].w;
                    acc[i][0] = fmaf(a, bv.x, acc[i][0]);
                    acc[i][1] = fmaf(a, bv.y, acc[i][1]);
                    acc[i][2] = fmaf(a, bv.z, acc[i][2]);
                    acc[i][3] = fmaf(a, bv.w, acc[i][3]);
                }
            }
        }

#pragma unroll
        for (int i = 0; i < 4; i++) {
            float p0 = 0.f, p1 = 0.f, p2 = 0.f;
#pragma unroll
            for (int j = 0; j < 4; j++) {
                float o = fmaxf(acc[i][j], 0.f);
                int kk = lane * 4 + j;
                p0 = fmaf(o, sW2[kk * N_OUT + 0], p0);
                p1 = fmaf(o, sW2[kk * N_OUT + 1], p1);
                p2 = fmaf(o, sW2[kk * N_OUT + 2], p2);
            }
#pragma unroll
            for (int off = 16; off > 0; off >>= 1) {
                p0 += __shfl_xor_sync(0xffffffffu, p0, off);
                p1 += __shfl_xor_sync(0xffffffffu, p1, off);
                p2 += __shfl_xor_sync(0xffffffffu, p2, off);
            }
            int n = n0 + i;
            if (lane == 0 && n < N_NODES) {
                out[(size_t)n * N_OUT + 0] = fmaxf(p0 + b2v0, 0.f);
                out[(size_t)n * N_OUT + 1] = fmaxf(p1 + b2v1, 0.f);
                out[(size_t)n * N_OUT + 2] = fmaxf(p2 + b2v2, 0.f);
            }
        }
        __syncwarp();
    }
}

// ======================= launch ============================================

extern "C" void kernel_launch(void* const* d_in, const int* in_sizes, int n_in,
                              void* d_out, int out_size) {
    const float* x       = (const float*)d_in[0];
    const int*   ei      = (const int*)d_in[1];
    const float* ea      = (const float*)d_in[2];
    const float* lin_w   = (const float*)d_in[3];
    const float* lin_b   = (const float*)d_in[4];
    const float* msg_w1  = (const float*)d_in[5];
    const float* msg_b1  = (const float*)d_in[6];
    const float* msg_w2  = (const float*)d_in[7];
    const float* msg_b2  = (const float*)d_in[8];
    const float* upd_w1  = (const float*)d_in[9];
    const float* upd_b1  = (const float*)d_in[10];
    const float* upd_w2  = (const float*)d_in[11];
    const float* upd_b2  = (const float*)d_in[12];
    const float* head_w1 = (const float*)d_in[13];
    const float* head_b1 = (const float*)d_in[14];
    const float* head_w2 = (const float*)d_in[15];
    const float* head_b2 = (const float*)d_in[16];
    float* out = (float*)d_out;

    const int* src = ei;
    const int* dst = ei + N_EDGES;

    int sm_count = 148;
    cudaDeviceGetAttribute(&sm_count, cudaDevAttrMultiProcessorCount, 0);

    const size_t smHd = (size_t)(H * H + H * N_OUT + TN * H) * sizeof(float);
    cudaFuncSetAttribute(edge_kernel, cudaFuncAttributeMaxDynamicSharedMemorySize, SM_EDGE_TOTAL);
    cudaFuncSetAttribute(node_kernel, cudaFuncAttributeMaxDynamicSharedMemorySize, NB_TOTAL);
    cudaFuncSetAttribute(head_kernel, cudaFuncAttributeMaxDynamicSharedMemorySize, (int)smHd);

    zero_cnt_kernel<<<(N_NODES + 255) / 256, 256>>>();
    deg_kernel<<<(N_EDGES + 255) / 256, 256>>>(dst);
    prep_kernel<<<1024, 256>>>(ea);     // inv + zero_agg + pack_ea fused
    lin_in_kernel<<<N_NODES, H>>>(x, lin_w, lin_b);

    for (int l = 0; l < N_LAYERS; l++) {
        edge_kernel<<<sm_count, 128 * NGRP, SM_EDGE_TOTAL>>>(
            src, dst,
            msg_w1 + (size_t)l * (H + ED) * H, msg_b1 + (size_t)l * H,
            msg_w2 + (size_t)l * H * H, msg_b2 + (size_t)l * H);
        node_kernel<<<sm_count, 256, NB_TOTAL>>>(
            upd_w1 + (size_t)l * 2 * H * H, upd_b1 + (size_t)l * H,
            upd_w2 + (size_t)l * H * H, upd_b2 + (size_t)l * H);
    }

    head_kernel<<<2 * sm_count, 256, smHd>>>(head_w1, head_b1, head_w2, head_b2, out);
}